// round 17
// baseline (speedup 1.0000x reference)
#include <cuda_runtime.h>
#include <cuda_bf16.h>

// Depthwise cross-correlation (VALID):
//   z_f: [128, 256, 7, 7]   (kernel, d_in[0])
//   x_f: [128, 256, 31, 31] (search, d_in[1])
//   out: [128, 256, 25, 25] fp32
//
// R8 redesign from ncu evidence (L1=95.7% = smem-bound, 4-way bank conflicts):
//  - 4 maps per CTA, 224 threads, 196 tasks (49 per map).
//  - Each thread computes a 4-row x 4-col output block (16 outputs).
//  - x staged in smem with mod-9 block-rotation swizzle:
//      block b of row r stored at position (b + r) % 9  -> breaks the
//      systematic bank-conflict pattern of the linear layout.
//  - x-row-outer mainloop: each of the 10 needed x rows loaded ONCE
//    (5 x LDS.64, 8B-aligned) and reused by up to 4 output rows.
//  - z in dual phase-shifted zero-padded layouts (zev/zod) -> packed
//    fma.rn.f32x2 throughout (2 lane-FMAs per fma-pipe op).
//  - Row-group 6 overlap-clamped to oy0=21 (rows 21-23 double-written with
//    identical values; avoids divergence and keeps x rows <= 30).

#define MAPS_PER_CTA 4
#define NTHREADS 224
#define NTASKS 196                  // 4 maps * 49 tasks
#define XS_STRIDE 36                // 9 blocks of 4 floats
#define XS_ROWS 31
#define XS_PER_MAP (XS_ROWS * XS_STRIDE)       // 1116
#define XS_TOTAL (MAPS_PER_CTA * XS_PER_MAP)   // 4464

typedef unsigned long long u64;

__device__ __forceinline__ u64 fma2(u64 a, u64 b, u64 c) {
    u64 d;
    asm("fma.rn.f32x2 %0, %1, %2, %3;" : "=l"(d) : "l"(a), "l"(b), "l"(c));
    return d;
}

__device__ __forceinline__ float hsum2(u64 p) {
    float lo, hi;
    asm("mov.b64 {%0, %1}, %2;" : "=f"(lo), "=f"(hi) : "l"(p));
    return lo + hi;
}

__global__ void __launch_bounds__(NTHREADS)
dwxcorr_kernel(const float* __restrict__ z, const float* __restrict__ x,
               float* __restrict__ out)
{
    __shared__ __align__(16) float xs[XS_TOTAL];
    __shared__ __align__(16) float zev[MAPS_PER_CTA][7][8];  // [z0..z6, 0]
    __shared__ __align__(16) float zod[MAPS_PER_CTA][7][8];  // [0, z0..z6]

    const int tid = threadIdx.x;
    const long long map0 = (long long)blockIdx.x * MAPS_PER_CTA;

    // ---- stage z (both phase layouts) ----
    if (tid < NTASKS) {
        int m = tid / 49, t = tid - m * 49;
        int ky = t / 7,  kx = t - ky * 7;
        float v = z[(map0 + m) * 49 + t];
        zev[m][ky][kx]     = v;
        zod[m][ky][kx + 1] = v;
    }
    if (tid < MAPS_PER_CTA * 7) {
        int m = tid / 7, ky = tid - m * 7;
        zev[m][ky][7] = 0.0f;
        zod[m][ky][0] = 0.0f;
    }

    // ---- stage x with mod-9 block-rotation swizzle ----
    {
        const float* xgb = x + map0 * (XS_ROWS * 31);
        #pragma unroll 4
        for (int i = tid; i < XS_TOTAL; i += NTHREADS) {
            int m   = i / XS_PER_MAP;
            int rem = i - m * XS_PER_MAP;
            int r   = rem / XS_STRIDE;
            int c   = rem - r * XS_STRIDE;
            float v = (c < 31) ? xgb[m * (XS_ROWS * 31) + r * 31 + c] : 0.0f;
            int pos = ((c >> 2) + r) % 9;
            xs[m * XS_PER_MAP + r * XS_STRIDE + pos * 4 + (c & 3)] = v;
        }
    }
    __syncthreads();

    if (tid >= NTASKS) return;

    const int m  = tid / 49;
    const int t  = tid - m * 49;
    const int r7 = t / 7;
    const int g  = t - r7 * 7;
    const int oy0 = (r7 == 6) ? 21 : r7 * 4;   // overlap clamp: rows 21-24
    const int c0  = g * 4;                     // first output column

    const float* xsm = xs + m * XS_PER_MAP;

    u64 acc[4][4];
    #pragma unroll
    for (int j = 0; j < 4; ++j)
        #pragma unroll
        for (int p = 0; p < 4; ++p) acc[j][p] = 0ull;

    int s = (g + oy0) % 9;                    // rotation of first block, first row
    const float* row = xsm + oy0 * XS_STRIDE;

    #pragma unroll
    for (int R = 0; R < 10; ++R) {            // x row = oy0 + R
        int p0 = s;
        int p1 = p0 + 1; if (p1 == 9) p1 = 0;
        int p2 = p1 + 1; if (p2 == 9) p2 = 0;
        s = p1;                               // next row's first block rotation

        // 5 even-aligned x pairs covering logical cols c0..c0+9 of this row
        u64 xp0 = *(const u64*)(row + p0 * 4);
        u64 xp1 = *(const u64*)(row + p0 * 4 + 2);
        u64 xp2 = *(const u64*)(row + p1 * 4);
        u64 xp3 = *(const u64*)(row + p1 * 4 + 2);
        u64 xp4 = *(const u64*)(row + p2 * 4);
        row += XS_STRIDE;

        #pragma unroll
        for (int j = 0; j < 4; ++j) {         // output row oy0 + j
            const int ky = R - j;
            if (ky < 0 || ky > 6) continue;   // compile-time pruned

            const ulonglong2* ze = (const ulonglong2*)zev[m][ky];
            const ulonglong2* zo = (const ulonglong2*)zod[m][ky];
            ulonglong2 ze01 = ze[0], ze23 = ze[1];
            ulonglong2 zo01 = zo[0], zo23 = zo[1];

            acc[j][0] = fma2(ze01.x, xp0, acc[j][0]);
            acc[j][1] = fma2(zo01.x, xp0, acc[j][1]);
            acc[j][2] = fma2(ze01.x, xp1, acc[j][2]);
            acc[j][3] = fma2(zo01.x, xp1, acc[j][3]);

            acc[j][0] = fma2(ze01.y, xp1, acc[j][0]);
            acc[j][1] = fma2(zo01.y, xp1, acc[j][1]);
            acc[j][2] = fma2(ze01.y, xp2, acc[j][2]);
            acc[j][3] = fma2(zo01.y, xp2, acc[j][3]);

            acc[j][0] = fma2(ze23.x, xp2, acc[j][0]);
            acc[j][1] = fma2(zo23.x, xp2, acc[j][1]);
            acc[j][2] = fma2(ze23.x, xp3, acc[j][2]);
            acc[j][3] = fma2(zo23.x, xp3, acc[j][3]);

            acc[j][0] = fma2(ze23.y, xp3, acc[j][0]);
            acc[j][1] = fma2(zo23.y, xp3, acc[j][1]);
            acc[j][2] = fma2(ze23.y, xp4, acc[j][2]);
            acc[j][3] = fma2(zo23.y, xp4, acc[j][3]);
        }
    }

    // ---- epilogue: 16 outputs (cols >= 25 masked; rows always valid) ----
    float* ob = out + (map0 + m) * 625 + c0;
    #pragma unroll
    for (int j = 0; j < 4; ++j) {
        float* og = ob + (oy0 + j) * 25;
        og[0] = hsum2(acc[j][0]);
        if (c0 < 24) {
            og[1] = hsum2(acc[j][1]);
            og[2] = hsum2(acc[j][2]);
            og[3] = hsum2(acc[j][3]);
        }
    }
}

extern "C" void kernel_launch(void* const* d_in, const int* in_sizes, int n_in,
                              void* d_out, int out_size)
{
    const float* z = (const float*)d_in[0];   // z_f [128,256,7,7]
    const float* x = (const float*)d_in[1];   // x_f [128,256,31,31]
    float* out = (float*)d_out;               // [128,256,25,25]

    dwxcorr_kernel<<<(128 * 256) / MAPS_PER_CTA, NTHREADS>>>(z, x, out);
}